// round 15
// baseline (speedup 1.0000x reference)
#include <cuda_runtime.h>
#include <cuda_fp16.h>
#include <math.h>
#include <stdint.h>

// ---------------------------------------------------------------------------
// Problem constants
// ---------------------------------------------------------------------------
#define BATCH      4096
#define NUM_PAIRS  28
#define PAIR_DIM   128
#define MACRO_DIM  256
#define NUM_SLOTS  64
#define D_ALL      3584          // NUM_PAIRS * PAIR_DIM
#define D_CAT      7168          // 2 * D_ALL
#define LN_EPS     1e-5f

// ---------------------------------------------------------------------------
// Scratch (device globals: allocation-free per harness rules)
// ---------------------------------------------------------------------------
__device__ half  g_attn_hi[BATCH * 128];                      // [attn_p | attn_m]
__device__ float g_V[(size_t)128 * D_ALL];                    // [Vp@W1top ; Vm@W1bot]
__device__ half  g_V_hi[(size_t)128 * D_ALL];
__device__ half  g_V_lo[(size_t)128 * D_ALL];
__device__ half  g_w2_hi[(size_t)D_ALL * D_ALL];
__device__ float g_h[(size_t)BATCH * D_ALL];
__device__ half  g_h_hi[(size_t)BATCH * D_ALL];
__device__ half  g_xcat_hi[(size_t)NUM_PAIRS * BATCH * 256];  // (p,b,256)
__device__ half  g_pw_hi[(size_t)NUM_PAIRS * 256 * 128];

// ---------------------------------------------------------------------------
// Small helpers
// ---------------------------------------------------------------------------
__device__ __forceinline__ uint32_t smem_u32(const void* p) {
    uint32_t a;
    asm("{ .reg .u64 t; cvta.to.shared.u64 t, %1; cvt.u32.u64 %0, t; }" : "=r"(a) : "l"(p));
    return a;
}
__device__ __forceinline__ void cp16(uint32_t dst, const void* src) {
    asm volatile("cp.async.cg.shared.global [%0], [%1], 16;" :: "r"(dst), "l"(src));
}
__device__ __forceinline__ void cp_commit() {
    asm volatile("cp.async.commit_group;" ::: "memory");
}
__device__ __forceinline__ void cp_wait0() {
    asm volatile("cp.async.wait_group 0;" ::: "memory");
}
__device__ __forceinline__ void cp_wait1() {
    asm volatile("cp.async.wait_group 1;" ::: "memory");
}
__device__ __forceinline__ void ldsm_x4(uint32_t* r, uint32_t addr) {
    asm volatile("ldmatrix.sync.aligned.m8n8.x4.shared.b16 {%0,%1,%2,%3}, [%4];"
        : "=r"(r[0]), "=r"(r[1]), "=r"(r[2]), "=r"(r[3]) : "r"(addr));
}
// x4 transposed: one instruction yields B fragments for TWO adjacent n8 tiles
// (lanes 0-15 address cols c..c+7, lanes 16-31 address cols c+8..c+15).
__device__ __forceinline__ void ldsm_x4_trans(uint32_t* r0, uint32_t* r1, uint32_t addr) {
    asm volatile("ldmatrix.sync.aligned.m8n8.x4.trans.shared.b16 {%0,%1,%2,%3}, [%4];"
        : "=r"(r0[0]), "=r"(r0[1]), "=r"(r1[0]), "=r"(r1[1]) : "r"(addr));
}
__device__ __forceinline__ void mma_f16(float* c, const uint32_t* a, const uint32_t* b) {
    asm volatile(
        "mma.sync.aligned.m16n8k16.row.col.f32.f16.f16.f32 "
        "{%0,%1,%2,%3}, {%4,%5,%6,%7}, {%8,%9}, {%0,%1,%2,%3};"
        : "+f"(c[0]), "+f"(c[1]), "+f"(c[2]), "+f"(c[3])
        : "r"(a[0]), "r"(a[1]), "r"(a[2]), "r"(a[3]), "r"(b[0]), "r"(b[1]));
}
__device__ __forceinline__ void split_hl(float v, half& h, half& l) {
    h = __float2half_rn(v);
    l = __float2half_rn(v - __half2float(h));
}

// ---------------------------------------------------------------------------
// Tensor-core fp16 GEMM: 128x128 tile, BK=32, NST-stage cp.async, 2 CTAs/SM.
//   TERMS==1: D = Ahi*Bhi
//   TERMS==2: D = Ahi*(Bhi+Blo)
//   TERMS==3: D = Ahi*Bhi + Ahi*Blo + Alo*Bhi
//   XCAT==1: write fp16 (hi only) into xcat fused-half (p = n-tile, b, 256).
//   swz==1:  flat-grid L2 swizzle: 7 groups of (4 n-tiles x 32 m-tiles).
// B fragments loaded with ldmatrix.x4.trans (2 n8 tiles per instruction).
// ---------------------------------------------------------------------------
#define TCB_K   32

template<int TERMS, int XCAT, int NST>
__global__ void __launch_bounds__(256, 2)
tc_gemm_kernel(const half* __restrict__ Ahi, const half* __restrict__ Alo,
               const half* __restrict__ Bhi, const half* __restrict__ Blo,
               const float* __restrict__ bias, float* __restrict__ C,
               half* __restrict__ Xhi,
               int M, int N, int K, int lda, int ldb, int ldc, int swz)
{
    constexpr int A_BYTES  = 10240;                    // 128 rows x 40 half
    constexpr int B_BYTES  = 8704;                     // 32 rows x 136 half
    constexpr int OFF_ALO  = A_BYTES;
    constexpr int OFF_BHI  = (TERMS == 3) ? 2 * A_BYTES : A_BYTES;
    constexpr int OFF_BLO  = OFF_BHI + B_BYTES;
    constexpr int STAGE    = (TERMS == 1) ? (OFF_BHI + B_BYTES)
                                          : (OFF_BLO + B_BYTES);

    extern __shared__ __align__(16) char sm[];
    const uint32_t smb = smem_u32(sm);

    int bx, by;
    if (swz) {
        int id = blockIdx.x;       // 896 blocks: 7 groups x (4 n x 32 m)
        int ng = id >> 7;
        int r  = id & 127;
        bx = ng * 4 + (r & 3);     // 0..27
        by = r >> 2;               // 0..31
    } else {
        bx = blockIdx.x; by = blockIdx.y;
    }

    const int tid  = threadIdx.x;
    const int wid  = tid >> 5;
    const int lane = tid & 31;
    const int wm   = wid & 1;
    const int wn   = wid >> 1;
    const int m0   = by * 128;
    const int n0   = bx * 128;

    const int tA = lane >> 3, rA = lane & 7;
    const int a_row_off = (tA & 1) * 8 + rA;
    const int a_kcol    = (tA >> 1) * 8;
    const uint32_t a_const = (uint32_t)((wm * 64 + a_row_off) * 40 + a_kcol) * 2;
    // x4.trans B addressing: lanes 0-15 -> rows k0..15 at col base; lanes
    // 16-31 -> rows k0..15 at col base + 8.
    const uint32_t b_const =
        (uint32_t)((lane & 15) * 136 + wn * 32 + (lane >> 4) * 8) * 2;

    float acc[4][4][4];
    #pragma unroll
    for (int i = 0; i < 4; i++)
        #pragma unroll
        for (int j = 0; j < 4; j++)
            #pragma unroll
            for (int q = 0; q < 4; q++) acc[i][j][q] = 0.f;

    const int nk = K / TCB_K;

    #define ISSUE_STAGE(slot, kt) do {                                         \
        uint32_t base = smb + (uint32_t)(slot) * STAGE;                        \
        int k0 = (kt) * TCB_K;                                                 \
        _Pragma("unroll")                                                      \
        for (int l = 0; l < 2; ++l) {                                          \
            int idx = tid + l * 256;                                           \
            int r = idx >> 2, c = idx & 3;                                     \
            cp16(base + r * 80 + c * 16,                                       \
                 Ahi + (size_t)(m0 + r) * lda + k0 + c * 8);                   \
            if constexpr (TERMS == 3)                                          \
                cp16(base + OFF_ALO + r * 80 + c * 16,                         \
                     Alo + (size_t)(m0 + r) * lda + k0 + c * 8);               \
        }                                                                      \
        _Pragma("unroll")                                                      \
        for (int l = 0; l < 2; ++l) {                                          \
            int idx = tid + l * 256;                                           \
            int r = idx >> 4, c = idx & 15;                                    \
            cp16(base + OFF_BHI + r * 272 + c * 16,                            \
                 Bhi + (size_t)(k0 + r) * ldb + n0 + c * 8);                   \
            if constexpr (TERMS >= 2)                                          \
                cp16(base + OFF_BLO + r * 272 + c * 16,                        \
                     Blo + (size_t)(k0 + r) * ldb + n0 + c * 8);               \
        }                                                                      \
    } while (0)

    #pragma unroll
    for (int s = 0; s < NST - 1; ++s) {
        if (s < nk) ISSUE_STAGE(s, s);
        cp_commit();
    }

    for (int kt = 0; kt < nk; ++kt) {
        asm volatile("cp.async.wait_group %0;" :: "n"(NST - 2) : "memory");
        __syncthreads();
        if (kt + NST - 1 < nk) { ISSUE_STAGE((kt + NST - 1) % NST, kt + NST - 1); }
        cp_commit();

        const int slot = kt % NST;
        const uint32_t base = smb + (uint32_t)slot * STAGE;
        const uint32_t aHb = base + a_const;
        const uint32_t aLb = base + OFF_ALO + a_const;
        const uint32_t bHb = base + OFF_BHI + b_const;
        const uint32_t bLb = base + OFF_BLO + b_const;

        #pragma unroll
        for (int kk = 0; kk < 2; ++kk) {
            uint32_t aH[4][4], aL[4][4], bH[4][2], bL[4][2];
            const uint32_t akk = (uint32_t)(kk * 16 * 2);
            const uint32_t bkk = (uint32_t)(kk * 16 * 136 * 2);
            #pragma unroll
            for (int mf = 0; mf < 4; ++mf) {
                uint32_t off = (uint32_t)(mf * 16 * 40) * 2 + akk;
                ldsm_x4(aH[mf], aHb + off);
                if constexpr (TERMS == 3) ldsm_x4(aL[mf], aLb + off);
            }
            #pragma unroll
            for (int nf = 0; nf < 4; nf += 2) {
                uint32_t off = (uint32_t)(nf * 8) * 2 + bkk;
                ldsm_x4_trans(bH[nf], bH[nf + 1], bHb + off);
                if constexpr (TERMS >= 2)
                    ldsm_x4_trans(bL[nf], bL[nf + 1], bLb + off);
            }
            #pragma unroll
            for (int mf = 0; mf < 4; ++mf)
                #pragma unroll
                for (int nf = 0; nf < 4; ++nf) {
                    mma_f16(acc[mf][nf], aH[mf], bH[nf]);
                    if constexpr (TERMS >= 2) mma_f16(acc[mf][nf], aH[mf], bL[nf]);
                    if constexpr (TERMS == 3) mma_f16(acc[mf][nf], aL[mf], bH[nf]);
                }
        }
    }
    #undef ISSUE_STAGE

    const int g  = lane >> 2;
    const int tg = lane & 3;
    #pragma unroll
    for (int mf = 0; mf < 4; ++mf) {
        int r0 = m0 + wm * 64 + mf * 16 + g;
        #pragma unroll
        for (int nf = 0; nf < 4; ++nf) {
            int c = wn * 32 + nf * 8 + tg * 2;
            float b0 = bias[n0 + c], b1 = bias[n0 + c + 1];
            float v00 = acc[mf][nf][0] + b0, v01 = acc[mf][nf][1] + b1;
            float v10 = acc[mf][nf][2] + b0, v11 = acc[mf][nf][3] + b1;
            if constexpr (XCAT == 1) {
                size_t d0 = ((size_t)bx * BATCH + r0) * 256 + 128 + c;
                size_t d1 = ((size_t)bx * BATCH + r0 + 8) * 256 + 128 + c;
                *reinterpret_cast<half2*>(Xhi + d0) =
                    __halves2half2(__float2half_rn(v00), __float2half_rn(v01));
                *reinterpret_cast<half2*>(Xhi + d1) =
                    __halves2half2(__float2half_rn(v10), __float2half_rn(v11));
            } else {
                *reinterpret_cast<float2*>(C + (size_t)r0 * ldc + n0 + c) =
                    make_float2(v00, v01);
                *reinterpret_cast<float2*>(C + (size_t)(r0 + 8) * ldc + n0 + c) =
                    make_float2(v10, v11);
            }
        }
    }
}

// ---------------------------------------------------------------------------
// Pair GEMM + fused LayerNorm: per p (blockIdx.y), C-tile 128(b) x 128(e),
// K=256, 1-term (A-hi x B-hi), LN over the 128-wide row in the epilogue.
// 2 CTAs/SM. B via ldmatrix.x4.trans.
// ---------------------------------------------------------------------------
__global__ void __launch_bounds__(256, 2)
pair_gemm_ln_kernel(const half* __restrict__ Xhi,
                    const half* __restrict__ PWhi,
                    const float* __restrict__ pb, const float* __restrict__ lng,
                    const float* __restrict__ lnb, float* __restrict__ out)
{
    constexpr int A_BYTES = 10240;
    constexpr int B_BYTES = 8704;
    constexpr int OFF_BHI = A_BYTES;
    constexpr int STAGE   = OFF_BHI + B_BYTES;   // 18944

    extern __shared__ __align__(16) char sm[];
    const uint32_t smb = smem_u32(sm);

    const int p   = blockIdx.y;
    const int m0  = blockIdx.x * 128;
    const int tid  = threadIdx.x;
    const int wid  = tid >> 5;
    const int lane = tid & 31;
    const int wm   = wid & 1;
    const int wn   = wid >> 1;

    const half* Ahi = Xhi + ((size_t)p * BATCH) * 256;
    const half* Bhi = PWhi + (size_t)p * 256 * 128;

    const int tA = lane >> 3, rA = lane & 7;
    const int a_row_off = (tA & 1) * 8 + rA;
    const int a_kcol    = (tA >> 1) * 8;
    const uint32_t a_const = (uint32_t)((wm * 64 + a_row_off) * 40 + a_kcol) * 2;
    const uint32_t b_const =
        (uint32_t)((lane & 15) * 136 + wn * 32 + (lane >> 4) * 8) * 2;

    float acc[4][4][4];
    #pragma unroll
    for (int i = 0; i < 4; i++)
        #pragma unroll
        for (int j = 0; j < 4; j++)
            #pragma unroll
            for (int q = 0; q < 4; q++) acc[i][j][q] = 0.f;

    #define P_ISSUE(slot, kt) do {                                             \
        uint32_t base = smb + (uint32_t)(slot) * STAGE;                        \
        int k0 = (kt) * TCB_K;                                                 \
        _Pragma("unroll")                                                      \
        for (int l = 0; l < 2; ++l) {                                          \
            int idx = tid + l * 256;                                           \
            int r = idx >> 2, c = idx & 3;                                     \
            cp16(base + r * 80 + c * 16,                                       \
                 Ahi + (size_t)(m0 + r) * 256 + k0 + c * 8);                   \
        }                                                                      \
        _Pragma("unroll")                                                      \
        for (int l = 0; l < 2; ++l) {                                          \
            int idx = tid + l * 256;                                           \
            int r = idx >> 4, c = idx & 15;                                    \
            cp16(base + OFF_BHI + r * 272 + c * 16,                            \
                 Bhi + (size_t)(k0 + r) * 128 + c * 8);                        \
        }                                                                      \
    } while (0)

    P_ISSUE(0, 0); cp_commit();

    #pragma unroll
    for (int kt = 0; kt < 8; ++kt) {           // K=256 -> 8 iters of 32
        cp_wait0();
        __syncthreads();
        if (kt + 1 < 8) { P_ISSUE((kt + 1) & 1, kt + 1); cp_commit(); }

        const uint32_t base = smb + (uint32_t)(kt & 1) * STAGE;
        const uint32_t aHb = base + a_const;
        const uint32_t bHb = base + OFF_BHI + b_const;

        #pragma unroll
        for (int kk = 0; kk < 2; ++kk) {
            uint32_t aH[4][4], bH[4][2];
            const uint32_t akk = (uint32_t)(kk * 16 * 2);
            const uint32_t bkk = (uint32_t)(kk * 16 * 136 * 2);
            #pragma unroll
            for (int mf = 0; mf < 4; ++mf) {
                uint32_t off = (uint32_t)(mf * 16 * 40) * 2 + akk;
                ldsm_x4(aH[mf], aHb + off);
            }
            #pragma unroll
            for (int nf = 0; nf < 4; nf += 2) {
                uint32_t off = (uint32_t)(nf * 8) * 2 + bkk;
                ldsm_x4_trans(bH[nf], bH[nf + 1], bHb + off);
            }
            #pragma unroll
            for (int mf = 0; mf < 4; ++mf)
                #pragma unroll
                for (int nf = 0; nf < 4; ++nf)
                    mma_f16(acc[mf][nf], aH[mf], bH[nf]);
        }
    }
    #undef P_ISSUE

    // ---- epilogue: stage (bias-added) outputs in smem, then LN per row
    __syncthreads();                       // done with stage buffers
    float* os = reinterpret_cast<float*>(sm);   // [128][132]
    const int g  = lane >> 2;
    const int tg = lane & 3;
    #pragma unroll
    for (int mf = 0; mf < 4; ++mf) {
        int r0 = wm * 64 + mf * 16 + g;
        #pragma unroll
        for (int nf = 0; nf < 4; ++nf) {
            int c = wn * 32 + nf * 8 + tg * 2;
            float b0 = pb[p * 128 + c], b1 = pb[p * 128 + c + 1];
            os[r0 * 132 + c]           = acc[mf][nf][0] + b0;
            os[r0 * 132 + c + 1]       = acc[mf][nf][1] + b1;
            os[(r0 + 8) * 132 + c]     = acc[mf][nf][2] + b0;
            os[(r0 + 8) * 132 + c + 1] = acc[mf][nf][3] + b1;
        }
    }
    __syncthreads();

    #pragma unroll
    for (int rr = 0; rr < 16; ++rr) {
        int r = wid * 16 + rr;
        const float* t = os + r * 132;
        float v0 = t[lane], v1 = t[lane + 32], v2 = t[lane + 64], v3 = t[lane + 96];
        float s = v0 + v1 + v2 + v3;
        #pragma unroll
        for (int o = 16; o > 0; o >>= 1) s += __shfl_xor_sync(0xffffffff, s, o);
        float mu = s * (1.0f / 128.0f);
        float d0 = v0 - mu, d1 = v1 - mu, d2 = v2 - mu, d3 = v3 - mu;
        float s2 = d0 * d0 + d1 * d1 + d2 * d2 + d3 * d3;
        #pragma unroll
        for (int o = 16; o > 0; o >>= 1) s2 += __shfl_xor_sync(0xffffffff, s2, o);
        float rstd = rsqrtf(s2 * (1.0f / 128.0f) + LN_EPS);

        int b = m0 + r;
        size_t base = (size_t)b * D_ALL + p * 128;
        int gi = p * 128;
        out[base + lane]      = d0 * rstd * lng[gi + lane]      + lnb[gi + lane];
        out[base + lane + 32] = d1 * rstd * lng[gi + lane + 32] + lnb[gi + lane + 32];
        out[base + lane + 64] = d2 * rstd * lng[gi + lane + 64] + lnb[gi + lane + 64];
        out[base + lane + 96] = d3 * rstd * lng[gi + lane + 96] + lnb[gi + lane + 96];
    }
}

// ---------------------------------------------------------------------------
// fp32 -> fp16 hi/lo split (elementwise, vectorized)
// ---------------------------------------------------------------------------
__global__ __launch_bounds__(256) void cvt_split_kernel(
    const float4* __restrict__ x, uint2* __restrict__ hi, uint2* __restrict__ lo, int n4)
{
    int i = blockIdx.x * 256 + threadIdx.x;
    if (i >= n4) return;
    float4 v = x[i];
    half h0, l0, h1, l1, h2, l2, h3, l3;
    split_hl(v.x, h0, l0); split_hl(v.y, h1, l1);
    split_hl(v.z, h2, l2); split_hl(v.w, h3, l3);
    half2 ha = __halves2half2(h0, h1), hb = __halves2half2(h2, h3);
    half2 la = __halves2half2(l0, l1), lb = __halves2half2(l2, l3);
    hi[i] = make_uint2(*reinterpret_cast<uint32_t*>(&ha), *reinterpret_cast<uint32_t*>(&hb));
    lo[i] = make_uint2(*reinterpret_cast<uint32_t*>(&la), *reinterpret_cast<uint32_t*>(&lb));
}

// fp32 -> fp16 hi only
__global__ __launch_bounds__(256) void cvt_hi_kernel(
    const float4* __restrict__ x, uint2* __restrict__ hi, int n4)
{
    int i = blockIdx.x * 256 + threadIdx.x;
    if (i >= n4) return;
    float4 v = x[i];
    half2 ha = __halves2half2(__float2half_rn(v.x), __float2half_rn(v.y));
    half2 hb = __halves2half2(__float2half_rn(v.z), __float2half_rn(v.w));
    hi[i] = make_uint2(*reinterpret_cast<uint32_t*>(&ha), *reinterpret_cast<uint32_t*>(&hb));
}

// ---------------------------------------------------------------------------
// attention weight kernels -> g_attn_hi (B, 128): [pair | macro]
// attn_pair also emits the xcat pair_states half (hi fp16) for row b.
// ---------------------------------------------------------------------------
__global__ __launch_bounds__(128) void attn_pair_kernel(
    const float* __restrict__ ps, const float* __restrict__ keys,
    half* __restrict__ ahi, half* __restrict__ xhi)
{
    int b = blockIdx.x, tid = threadIdx.x;
    __shared__ float q[PAIR_DIM];
    __shared__ float sc[NUM_SLOTS];
    __shared__ float red[NUM_SLOTS];

    const float* psrow = ps + (size_t)b * D_ALL;

    float s = 0.f;
    #pragma unroll
    for (int p = 0; p < NUM_PAIRS; p++)
        s += psrow[p * PAIR_DIM + tid];
    q[tid] = s * (1.0f / NUM_PAIRS);
    __syncthreads();

    if (tid < NUM_SLOTS) {
        float acc = 0.f;
        #pragma unroll 4
        for (int d = 0; d < PAIR_DIM; d++)
            acc = fmaf(q[d], keys[tid * PAIR_DIM + d], acc);
        sc[tid] = acc * 0.08838834764831845f;
    }
    __syncthreads();

    if (tid < NUM_SLOTS) red[tid] = sc[tid];
    __syncthreads();
    for (int o = 32; o > 0; o >>= 1) {
        if (tid < o) red[tid] = fmaxf(red[tid], red[tid + o]);
        __syncthreads();
    }
    float mx = red[0];
    __syncthreads();

    float e = 0.f;
    if (tid < NUM_SLOTS) { e = expf(sc[tid] - mx); red[tid] = e; }
    __syncthreads();
    for (int o = 32; o > 0; o >>= 1) {
        if (tid < o) red[tid] += red[tid + o];
        __syncthreads();
    }
    if (tid < NUM_SLOTS)
        ahi[(size_t)b * 128 + tid] = __float2half_rn(e / red[0]);

    // ---- fused: write xcat pair_states half (hi fp16), row b, all 28 pairs
    #pragma unroll
    for (int p = 0; p < NUM_PAIRS; p++) {
        float v = psrow[p * PAIR_DIM + tid];
        xhi[((size_t)p * BATCH + b) * 256 + tid] = __float2half_rn(v);
    }
}

__global__ __launch_bounds__(128) void attn_macro_kernel(
    const float* __restrict__ ms, const float* __restrict__ keys,
    half* __restrict__ ahi)
{
    int b = blockIdx.x, tid = threadIdx.x;
    __shared__ float q[MACRO_DIM];
    __shared__ float sc[NUM_SLOTS];
    __shared__ float red[NUM_SLOTS];

    q[tid]       = ms[(size_t)b * MACRO_DIM + tid];
    q[tid + 128] = ms[(size_t)b * MACRO_DIM + tid + 128];
    __syncthreads();

    if (tid < NUM_SLOTS) {
        float acc = 0.f;
        #pragma unroll 4
        for (int d = 0; d < MACRO_DIM; d++)
            acc = fmaf(q[d], keys[tid * MACRO_DIM + d], acc);
        sc[tid] = acc * 0.0625f;
    }
    __syncthreads();

    if (tid < NUM_SLOTS) red[tid] = sc[tid];
    __syncthreads();
    for (int o = 32; o > 0; o >>= 1) {
        if (tid < o) red[tid] = fmaxf(red[tid], red[tid + o]);
        __syncthreads();
    }
    float mx = red[0];
    __syncthreads();

    float e = 0.f;
    if (tid < NUM_SLOTS) { e = expf(sc[tid] - mx); red[tid] = e; }
    __syncthreads();
    for (int o = 32; o > 0; o >>= 1) {
        if (tid < o) red[tid] += red[tid + o];
        __syncthreads();
    }
    if (tid < NUM_SLOTS)
        ahi[(size_t)b * 128 + 64 + tid] = __float2half_rn(e / red[0]);
}

// ---------------------------------------------------------------------------
// Zero kernel (for g_V before atomic fold)
// ---------------------------------------------------------------------------
__global__ __launch_bounds__(256) void zero_kernel(float* __restrict__ p, int n)
{
    int i = blockIdx.x * 256 + threadIdx.x;
    if (i < n) p[i] = 0.f;
}

// ---------------------------------------------------------------------------
// Fold (v5 config): V[z*64 + m, n] += sum_k vals_z[m,k] * W1[z*3584 + k, n]
// Tile 64(M) x 128(N), BK=16, split-K=16, 3-stage cp.async.
// Inner loop: 4-k blocks, broadcast LDS.128 A loads. 3 CTAs/SM.
// ---------------------------------------------------------------------------
#define FK_KS   16
#define FK_KCH  (D_ALL / FK_KS)    // 224
#define FK_BK   16
#define FK_BN   128
#define FK_AS_B   5120
#define FK_STAGE  13568
#define FK_NST    3

__global__ __launch_bounds__(256, 3) void fold_kernel(
    const float* __restrict__ vals_p, const float* __restrict__ vals_m,
    const float* __restrict__ w1, float* __restrict__ V)
{
    extern __shared__ __align__(16) char sm[];
    const uint32_t smb = smem_u32(sm);

    const int nb = blockIdx.x;
    const int ks = blockIdx.y;
    const int z  = blockIdx.z;
    const float* vals = z ? vals_m : vals_p;
    const float* W    = w1 + (size_t)z * D_ALL * D_ALL;
    float* Vout       = V  + (size_t)z * 64 * D_ALL;

    const int tid = threadIdx.x;
    const int ty  = tid >> 5;
    const int tx  = tid & 31;
    const int n0  = nb * FK_BN;
    const int kb  = ks * FK_KCH;

    float acc[8][4];
    #pragma unroll
    for (int i = 0; i < 8; i++)
        #pragma unroll
        for (int j = 0; j < 4; j++) acc[i][j] = 0.f;

    #define FK_ISSUE(slot, k0) do {                                            \
        uint32_t base = smb + (uint32_t)(slot) * FK_STAGE;                     \
        {   int m = tid >> 2, c = tid & 3;                                     \
            cp16(base + m * 80 + c * 16,                                       \
                 vals + (size_t)m * D_ALL + (k0) + c * 4); }                   \
        _Pragma("unroll")                                                      \
        for (int l = 0; l < 2; ++l) {                                          \
            int idx = tid + l * 256;                                           \
            int r = idx >> 5, c4 = idx & 31;                                   \
            cp16(base + FK_AS_B + r * 528 + c4 * 16,                           \
                 W + (size_t)((k0) + r) * D_ALL + n0 + c4 * 4); }              \
    } while (0)

    FK_ISSUE(0, kb); cp_commit();
    FK_ISSUE(1, kb + FK_BK); cp_commit();

    const int niter = FK_KCH / FK_BK;   // 14
    for (int it = 0; it < niter; ++it) {
        cp_wait1();
        __syncthreads();
        if (it + 2 < niter) { FK_ISSUE((it + 2) % FK_NST, kb + (it + 2) * FK_BK); }
        cp_commit();

        const int slot = it % FK_NST;
        const float* As = reinterpret_cast<const float*>(sm + slot * FK_STAGE);
        const float* Bs = reinterpret_cast<const float*>(sm + slot * FK_STAGE + FK_AS_B);

        #pragma unroll
        for (int kb4 = 0; kb4 < FK_BK / 4; ++kb4) {
            float4 a4[8];
            #pragma unroll
            for (int i = 0; i < 8; i++)
                a4[i] = *reinterpret_cast<const float4*>(As + (ty * 8 + i) * 20 + kb4 * 4);
            const float* af = reinterpret_cast<const float*>(a4);
            #pragma unroll
            for (int kk = 0; kk < 4; ++kk) {
                float4 bq = *reinterpret_cast<const float4*>(
                    Bs + (kb4 * 4 + kk) * 132 + tx * 4);
                float b[4] = {bq.x, bq.y, bq.z, bq.w};
                #pragma unroll
                for (int i = 0; i < 8; i++) {
                    float a = af[i * 4 + kk];
                    #pragma unroll
                    for (int j = 0; j < 4; j++)
                        acc[i][j] = fmaf(a, b[j], acc[i][j]);
                }
            }
        }
    }
    #undef FK_ISSUE

    #pragma unroll
    for (int i = 0; i < 8; i++) {
        int m = ty * 8 + i;
        #pragma unroll
        for (int j = 0; j < 4; j++)
            atomicAdd(Vout + (size_t)m * D_ALL + n0 + tx * 4 + j, acc[i][j]);
    }
}

// ---------------------------------------------------------------------------
// LayerNorm + exact GELU over rows of length D_ALL; writes fp16 hi.
// ---------------------------------------------------------------------------
__global__ __launch_bounds__(512) void ln_gelu_kernel(
    const float* __restrict__ h, const float* __restrict__ g, const float* __restrict__ b,
    half* __restrict__ ohi)
{
    __shared__ float row[D_ALL];
    __shared__ float reds[16], reds2[16];
    int bi = blockIdx.x, tid = threadIdx.x;
    const float4* hrow = reinterpret_cast<const float4*>(h + (size_t)bi * D_ALL);
    float4* rowv = reinterpret_cast<float4*>(row);

    float s = 0.f, s2 = 0.f;
    for (int i = tid; i < D_ALL / 4; i += 512) {
        float4 v = hrow[i];
        rowv[i] = v;
        s  += v.x + v.y + v.z + v.w;
        s2 += v.x * v.x + v.y * v.y + v.z * v.z + v.w * v.w;
    }
    #pragma unroll
    for (int o = 16; o > 0; o >>= 1) {
        s  += __shfl_xor_sync(0xffffffff, s, o);
        s2 += __shfl_xor_sync(0xffffffff, s2, o);
    }
    int warp = tid >> 5, lane = tid & 31;
    if (lane == 0) { reds[warp] = s; reds2[warp] = s2; }
    __syncthreads();
    if (warp == 0) {
        float a = (lane < 16) ? reds[lane] : 0.f;
        float a2 = (lane < 16) ? reds2[lane] : 0.f;
        #pragma unroll
        for (int o = 8; o > 0; o >>= 1) {
            a  += __shfl_xor_sync(0xffffffff, a, o);
            a2 += __shfl_xor_sync(0xffffffff, a2, o);
        }
        if (lane == 0) { reds[0] = a; reds2[0] = a2; }
    }
    __syncthreads();
    float mu = reds[0] * (1.0f / D_ALL);
    float var = reds2[0] * (1.0f / D_ALL) - mu * mu;
    float rstd = rsqrtf(var + LN_EPS);

    half* orow = ohi + (size_t)bi * D_ALL;
    for (int i = tid; i < D_ALL / 4; i += 512) {
        float4 v = rowv[i];
        float4 gg = reinterpret_cast<const float4*>(g)[i];
        float4 bb = reinterpret_cast<const float4*>(b)[i];
        float y0 = (v.x - mu) * rstd * gg.x + bb.x;
        float y1 = (v.y - mu) * rstd * gg.y + bb.y;
        float y2 = (v.z - mu) * rstd * gg.z + bb.z;
        float y3 = (v.w - mu) * rstd * gg.w + bb.w;
        const float k = 0.70710678118654752f;
        half o0 = __float2half_rn(0.5f * y0 * (1.0f + erff(y0 * k)));
        half o1 = __float2half_rn(0.5f * y1 * (1.0f + erff(y1 * k)));
        half o2 = __float2half_rn(0.5f * y2 * (1.0f + erff(y2 * k)));
        half o3 = __float2half_rn(0.5f * y3 * (1.0f + erff(y3 * k)));
        half h4[4] = {o0, o1, o2, o3};
        *reinterpret_cast<uint2*>(orow + i * 4) = *reinterpret_cast<uint2*>(h4);
    }
}

// ---------------------------------------------------------------------------
// Launch
// ---------------------------------------------------------------------------
extern "C" void kernel_launch(void* const* d_in, const int* in_sizes, int n_in,
                              void* d_out, int out_size)
{
    const float* pair_states    = (const float*)d_in[0];
    const float* macro_state    = (const float*)d_in[1];
    const float* mem_pair_keys  = (const float*)d_in[2];
    const float* mem_pair_vals  = (const float*)d_in[3];
    const float* mem_macro_keys = (const float*)d_in[4];
    const float* mem_macro_vals = (const float*)d_in[5];
    const float* fusion_w1      = (const float*)d_in[6];
    const float* fusion_b1      = (const float*)d_in[7];
    const float* fusion_ln_g    = (const float*)d_in[8];
    const float* fusion_ln_b    = (const float*)d_in[9];
    const float* fusion_w2      = (const float*)d_in[10];
    const float* fusion_b2      = (const float*)d_in[11];
    const float* pair_w         = (const float*)d_in[12];
    const float* pair_b         = (const float*)d_in[13];
    const float* pair_ln_g      = (const float*)d_in[14];
    const float* pair_ln_b      = (const float*)d_in[15];
    float* out = (float*)d_out;

    float *V, *h;
    half *a_hi, *V_hi, *V_lo, *w2_hi, *h_hi, *x_hi, *pw_hi;
    cudaGetSymbolAddress((void**)&a_hi,  g_attn_hi);
    cudaGetSymbolAddress((void**)&V,     g_V);
    cudaGetSymbolAddress((void**)&V_hi,  g_V_hi);
    cudaGetSymbolAddress((void**)&V_lo,  g_V_lo);
    cudaGetSymbolAddress((void**)&w2_hi, g_w2_hi);
    cudaGetSymbolAddress((void**)&h,     g_h);
    cudaGetSymbolAddress((void**)&h_hi,  g_h_hi);
    cudaGetSymbolAddress((void**)&x_hi,  g_xcat_hi);
    cudaGetSymbolAddress((void**)&pw_hi, g_pw_hi);

    const int SMEM_G2 = 4 * 18944;               // 75776 (1-term, 4 stages)
    const int SMEM_G1 = 3 * 27648;               // 82944 (2-term, 3 stages)
    const int SMEMP   = 128 * 132 * 4;           // 67584 (pair: os dominates)
    const int SMEMF   = FK_NST * FK_STAGE;       // 40704 (fold, 3-stage)
    cudaFuncSetAttribute(tc_gemm_kernel<1, 1, 4>,
                         cudaFuncAttributeMaxDynamicSharedMemorySize, SMEM_G2);
    cudaFuncSetAttribute(tc_gemm_kernel<2, 0, 3>,
                         cudaFuncAttributeMaxDynamicSharedMemorySize, SMEM_G1);
    cudaFuncSetAttribute(pair_gemm_ln_kernel,
                         cudaFuncAttributeMaxDynamicSharedMemorySize, SMEMP);
    cudaFuncSetAttribute(fold_kernel,
                         cudaFuncAttributeMaxDynamicSharedMemorySize, SMEMF);

    // 1) attention weights -> fp16 hi (B, 128); attn_pair also fills xcat
    //    pair_states half
    attn_pair_kernel<<<BATCH, 128>>>(pair_states, mem_pair_keys, a_hi, x_hi);
    attn_macro_kernel<<<BATCH, 128>>>(macro_state, mem_macro_keys, a_hi);

    // 2) fold: V = [vals_p @ W1top ; vals_m @ W1bot]  (128 x 3584 fp32)
    zero_kernel<<<(128 * D_ALL + 255) / 256, 256>>>(V, 128 * D_ALL);
    fold_kernel<<<dim3(D_ALL / FK_BN, FK_KS, 2), 256, SMEMF>>>(
        mem_pair_vals, mem_macro_vals, fusion_w1, V);
    {
        int n4 = (128 * D_ALL) / 4;
        cvt_split_kernel<<<(n4 + 255) / 256, 256>>>(
            (const float4*)V, (uint2*)V_hi, (uint2*)V_lo, n4);
    }

    // 2b) weight converts (hi-only)
    {
        int n4 = (D_ALL * D_ALL) / 4;
        cvt_hi_kernel<<<(n4 + 255) / 256, 256>>>(
            (const float4*)fusion_w2, (uint2*)w2_hi, n4);
        n4 = (NUM_PAIRS * 256 * 128) / 4;
        cvt_hi_kernel<<<(n4 + 255) / 256, 256>>>(
            (const float4*)pair_w, (uint2*)pw_hi, n4);
    }

    // 3) h = attn @ V + b1  (tensor cores, 2-term: A hi, B hi+lo, K=128)
    tc_gemm_kernel<2, 0, 3><<<dim3(D_ALL / 128, BATCH / 128), 256, SMEM_G1>>>(
        a_hi, nullptr, V_hi, V_lo, fusion_b1, h, nullptr,
        BATCH, D_ALL, 128, 128, D_ALL, D_ALL, 0);

    // 4) LN + GELU -> h_hi; GEMM2 (fp16 1-term, 4-stage) with xcat epilogue
    ln_gelu_kernel<<<BATCH, 512>>>(h, fusion_ln_g, fusion_ln_b, h_hi);
    tc_gemm_kernel<1, 1, 4><<<dim3((D_ALL / 128) * (BATCH / 128), 1), 256, SMEM_G2>>>(
        h_hi, nullptr, w2_hi, nullptr, fusion_b2, nullptr, x_hi,
        BATCH, D_ALL, D_ALL, D_ALL, D_ALL, D_ALL, 1);

    // 5) per-pair linear (1-term) + fused LN -> output
    pair_gemm_ln_kernel<<<dim3(BATCH / 128, NUM_PAIRS), 256, SMEMP>>>(
        x_hi, pw_hi, pair_b, pair_ln_g, pair_ln_b, out);
}